// round 1
// baseline (speedup 1.0000x reference)
#include <cuda_runtime.h>
#include <math.h>
#include <stdint.h>

#define N_MLP  16
#define LATENT 1024
#define S0     512
#define S1     256
#define S2     128
#define OUTD   3
#define TG     64          // grid points per CTA
#define NTHR   256

// ---------------- device scratch (no allocs allowed) ----------------
__device__ float g_W1t[N_MLP * S0 * S1];   // [m][k(S0)][o(S1)]
__device__ float g_W2t[N_MLP * S1 * S2];   // [m][k(S1)][o(S2)]
__device__ float g_c0 [N_MLP * S0];        // W0a@x0 + b0a + b0b

// ---------------- prep: c0[m][o] = dot(W0a[m][o],x0) + b0a + b0b ----
__global__ void prep_c0(const float* __restrict__ x0,
                        const float* __restrict__ W0a,
                        const float* __restrict__ b0a,
                        const float* __restrict__ b0b) {
    int w    = (blockIdx.x * blockDim.x + threadIdx.x) >> 5;
    int lane = threadIdx.x & 31;
    if (w >= N_MLP * S0) return;
    const float* row = W0a + (size_t)w * LATENT;
    float s = 0.f;
    #pragma unroll 4
    for (int i = lane; i < LATENT; i += 32) s += row[i] * x0[i];
    #pragma unroll
    for (int off = 16; off; off >>= 1) s += __shfl_xor_sync(0xffffffffu, s, off);
    if (lane == 0) g_c0[w] = s + b0a[w] + b0b[w];
}

// ---------------- prep: transpose W1,W2 to [m][k][o] -----------------
__global__ void prep_transpose(const float* __restrict__ W1,
                               const float* __restrict__ W2) {
    const int total1 = N_MLP * S0 * S1;
    for (int idx = blockIdx.x * blockDim.x + threadIdx.x; idx < total1;
         idx += gridDim.x * blockDim.x) {
        int o = idx % S1;
        int k = (idx / S1) % S0;
        int m = idx / (S1 * S0);
        g_W1t[idx] = W1[((size_t)m * S1 + o) * S0 + k];
    }
    const int total2 = N_MLP * S1 * S2;
    for (int idx = blockIdx.x * blockDim.x + threadIdx.x; idx < total2;
         idx += gridDim.x * blockDim.x) {
        int o = idx % S2;
        int k = (idx / S2) % S1;
        int m = idx / (S2 * S1);
        g_W2t[idx] = W2[((size_t)m * S2 + o) * S1 + k];
    }
}

// ---------------- SMEM layout (floats) ------------------------------
// h0s  : [S0][TG]        0      .. 32768      (aliased by h2s [S2][65])
// h1s  : [S1][65]        32768  .. 49408
// w1s  : [16][S1]        49408  .. 53504      (aliased by w2s [16][S2])
// c0s  : 512             53504
// wxs  : 512             54016
// wys  : 512             54528
// b1s  : 256             55040
// b2s  : 128             55296
// w3s  : 384             55424
// b3s  : 4               55808
// gxs  : 64              55812
// gys  : 64              55876
// total 55940 floats = 223760 bytes
#define SMEM_FLOATS 55940

__global__ __launch_bounds__(NTHR, 1)
void mlp_fused(const float* __restrict__ W0b,
               const float* __restrict__ b1,
               const float* __restrict__ b2,
               const float* __restrict__ W3,
               const float* __restrict__ b3,
               const int*   __restrict__ n_ptr,
               float*       __restrict__ out,
               int G) {
    extern __shared__ float sm[];
    float* h0s = sm;                 // 32768, also h2s
    float* h1s = sm + 32768;         // 16640 (pitch 65)
    float* w1s = sm + 49408;         // 4096, also w2s
    float* c0s = sm + 53504;
    float* wxs = sm + 54016;
    float* wys = sm + 54528;
    float* b1s = sm + 55040;
    float* b2s = sm + 55296;
    float* w3s = sm + 55424;
    float* b3s = sm + 55808;
    float* gxs = sm + 55812;
    float* gys = sm + 55876;

    const int m    = blockIdx.y;
    const int tile = blockIdx.x;
    const int tid  = threadIdx.x;
    const int n    = *n_ptr;

    // ---- stage per-MLP constants ----
    for (int i = tid; i < S0; i += NTHR) {
        c0s[i] = g_c0[m * S0 + i];
        wxs[i] = W0b[((size_t)m * S0 + i) * 2 + 0];
        wys[i] = W0b[((size_t)m * S0 + i) * 2 + 1];
    }
    for (int i = tid; i < S1; i += NTHR) b1s[i] = b1[m * S1 + i];
    for (int i = tid; i < S2; i += NTHR) b2s[i] = b2[m * S2 + i];
    for (int i = tid; i < OUTD * S2; i += NTHR) w3s[i] = W3[(size_t)m * OUTD * S2 + i];
    if (tid < OUTD) b3s[tid] = b3[m * OUTD + tid];
    if (tid < TG) {
        int p = tile * TG + tid;
        int px = 0, py = 0;
        if (p < G) { px = p % n; py = p / n; }
        float step = 2.0f / (float)(n - 1);
        gxs[tid] = -1.0f + step * (float)px;
        gys[tid] = -1.0f + step * (float)py;
    }
    __syncthreads();

    // ---- layer 0: h0s[o][g] = relu(c0[o] + wx[o]*gx + wy[o]*gy) ----
    for (int idx = tid; idx < S0 * TG; idx += NTHR) {
        int o = idx >> 6, g = idx & 63;
        float v = fmaf(wxs[o], gxs[g], fmaf(wys[o], gys[g], c0s[o]));
        h0s[idx] = fmaxf(v, 0.f);
    }

    // ---- layer 1: [TG x S1] = relu(h0[TG x S0] @ W1t) ----
    const int tcol = tid & 31, trow = tid >> 5;
    const int g0 = trow * 8;
    {
        const float* W1tm = g_W1t + (size_t)m * S0 * S1;
        const int o0 = tcol * 8;
        float acc[8][8];
        #pragma unroll
        for (int i = 0; i < 8; ++i)
            #pragma unroll
            for (int j = 0; j < 8; ++j) acc[i][j] = 0.f;

        for (int k0 = 0; k0 < S0; k0 += 16) {
            __syncthreads();   // previous stage consumed / layer0 writes done
            #pragma unroll
            for (int i = 0; i < 4; ++i) {
                int t = tid + i * NTHR;      // 1024 float4 per stage
                ((float4*)w1s)[t] = ((const float4*)(W1tm + (size_t)k0 * S1))[t];
            }
            __syncthreads();
            #pragma unroll
            for (int k = 0; k < 16; ++k) {
                const float* hr = h0s + (k0 + k) * TG + g0;
                float4 a0 = *(const float4*)hr;
                float4 a1 = *(const float4*)(hr + 4);
                const float* wr = w1s + k * S1 + o0;
                float4 c0v = *(const float4*)wr;
                float4 c1v = *(const float4*)(wr + 4);
                float av[8] = {a0.x, a0.y, a0.z, a0.w, a1.x, a1.y, a1.z, a1.w};
                float bv[8] = {c0v.x, c0v.y, c0v.z, c0v.w, c1v.x, c1v.y, c1v.z, c1v.w};
                #pragma unroll
                for (int i = 0; i < 8; ++i)
                    #pragma unroll
                    for (int j = 0; j < 8; ++j)
                        acc[i][j] = fmaf(av[i], bv[j], acc[i][j]);
            }
        }
        // epilogue -> h1s[o][g], pitch 65
        #pragma unroll
        for (int j = 0; j < 8; ++j) {
            float bb = b1s[o0 + j];
            #pragma unroll
            for (int i = 0; i < 8; ++i)
                h1s[(o0 + j) * 65 + (g0 + i)] = fmaxf(acc[i][j] + bb, 0.f);
        }
    }

    // ---- layer 2: [TG x S2] = relu(h1[TG x S1] @ W2t) ----
    {
        const float* W2tm = g_W2t + (size_t)m * S1 * S2;
        float* w2s = w1s;                  // alias
        const int o0 = tcol * 4;
        float acc[8][4];
        #pragma unroll
        for (int i = 0; i < 8; ++i)
            #pragma unroll
            for (int j = 0; j < 4; ++j) acc[i][j] = 0.f;

        for (int k0 = 0; k0 < S1; k0 += 16) {
            __syncthreads();   // h1s fully written / w1s consumers done
            #pragma unroll
            for (int i = 0; i < 2; ++i) {
                int t = tid + i * NTHR;      // 512 float4 per stage
                ((float4*)w2s)[t] = ((const float4*)(W2tm + (size_t)k0 * S2))[t];
            }
            __syncthreads();
            #pragma unroll
            for (int k = 0; k < 16; ++k) {
                const float* hr = h1s + (k0 + k) * 65 + g0;   // broadcast reads
                float av[8];
                #pragma unroll
                for (int i = 0; i < 8; ++i) av[i] = hr[i];
                float4 c0v = *(const float4*)(w2s + k * S2 + o0);
                float bv[4] = {c0v.x, c0v.y, c0v.z, c0v.w};
                #pragma unroll
                for (int i = 0; i < 8; ++i)
                    #pragma unroll
                    for (int j = 0; j < 4; ++j)
                        acc[i][j] = fmaf(av[i], bv[j], acc[i][j]);
            }
        }
        // epilogue -> h2s[o][g], pitch 65 (aliases dead h0s)
        float* h2s = h0s;
        #pragma unroll
        for (int j = 0; j < 4; ++j) {
            float bb = b2s[o0 + j];
            #pragma unroll
            for (int i = 0; i < 8; ++i)
                h2s[(o0 + j) * 65 + (g0 + i)] = fmaxf(acc[i][j] + bb, 0.f);
        }
    }
    __syncthreads();

    // ---- layer 3: out[g][o] = tanh(h2[g] . W3[o] + b3[o]) ----
    if (tid < TG * OUTD) {
        const float* h2s = h0s;
        int g = tid & 63;
        int o = tid >> 6;
        float s = b3s[o];
        const float* wr = w3s + o * S2;
        #pragma unroll 8
        for (int k = 0; k < S2; ++k) s = fmaf(h2s[k * 65 + g], wr[k], s);
        int p = tile * TG + g;
        if (p < G) out[((size_t)m * G + p) * OUTD + o] = tanhf(s);
    }
}

// ---------------- host launcher --------------------------------------
extern "C" void kernel_launch(void* const* d_in, const int* in_sizes, int n_in,
                              void* d_out, int out_size) {
    const float* x0  = (const float*)d_in[0];
    const float* W0a = (const float*)d_in[1];
    const float* b0a = (const float*)d_in[2];
    const float* W0b = (const float*)d_in[3];
    const float* b0b = (const float*)d_in[4];
    const float* W1  = (const float*)d_in[5];
    const float* b1  = (const float*)d_in[6];
    const float* W2  = (const float*)d_in[7];
    const float* b2  = (const float*)d_in[8];
    const float* W3  = (const float*)d_in[9];
    const float* b3  = (const float*)d_in[10];
    const int*   np  = (const int*)d_in[11];

    int G = out_size / (N_MLP * OUTD);   // grid points per MLP

    // prep
    prep_c0<<<(N_MLP * S0 * 32 + NTHR - 1) / NTHR, NTHR>>>(x0, W0a, b0a, b0b);
    prep_transpose<<<1024, NTHR>>>(W1, W2);

    // main fused kernel
    static bool attr_set = false;
    if (!attr_set) {
        cudaFuncSetAttribute(mlp_fused, cudaFuncAttributeMaxDynamicSharedMemorySize,
                             SMEM_FLOATS * sizeof(float));
        attr_set = true;
    }
    dim3 grid((G + TG - 1) / TG, N_MLP);
    mlp_fused<<<grid, NTHR, SMEM_FLOATS * sizeof(float)>>>(
        W0b, b1, b2, W3, b3, np, (float*)d_out, G);
}

// round 2
// speedup vs baseline: 1.0145x; 1.0145x over previous
#include <cuda_runtime.h>
#include <math.h>
#include <stdint.h>

#define N_MLP  16
#define LATENT 1024
#define S0     512
#define S1     256
#define S2     128
#define OUTD   3
#define TG     64          // grid points per CTA
#define NTHR   256

typedef unsigned long long ull;

// ---------------- packed f32x2 helpers --------------------------------
__device__ __forceinline__ ull pack2(float x, float y) {
    ull r; asm("mov.b64 %0, {%1, %2};" : "=l"(r) : "f"(x), "f"(y)); return r;
}
__device__ __forceinline__ ull ffma2(ull a, ull b, ull c) {
    ull d; asm("fma.rn.f32x2 %0, %1, %2, %3;" : "=l"(d) : "l"(a), "l"(b), "l"(c));
    return d;
}
__device__ __forceinline__ void unpack2(ull v, float& x, float& y) {
    asm("mov.b64 {%0, %1}, %2;" : "=f"(x), "=f"(y) : "l"(v));
}

// ---------------- device scratch (no allocs allowed) ----------------
__device__ float g_W1t[N_MLP * S0 * S1];   // [m][k(S0)][o(S1)]
__device__ float g_W2t[N_MLP * S1 * S2];   // [m][k(S1)][o(S2)]
__device__ float g_c0 [N_MLP * S0];        // W0a@x0 + b0a + b0b

// ---------------- prep: c0[m][o] = dot(W0a[m][o],x0) + b0a + b0b ----
__global__ void prep_c0(const float* __restrict__ x0,
                        const float* __restrict__ W0a,
                        const float* __restrict__ b0a,
                        const float* __restrict__ b0b) {
    int w    = (blockIdx.x * blockDim.x + threadIdx.x) >> 5;
    int lane = threadIdx.x & 31;
    if (w >= N_MLP * S0) return;
    const float* row = W0a + (size_t)w * LATENT;
    float s = 0.f;
    #pragma unroll 4
    for (int i = lane; i < LATENT; i += 32) s += row[i] * x0[i];
    #pragma unroll
    for (int off = 16; off; off >>= 1) s += __shfl_xor_sync(0xffffffffu, s, off);
    if (lane == 0) g_c0[w] = s + b0a[w] + b0b[w];
}

// ---------------- prep: transpose W1,W2 to [m][k][o] -----------------
__global__ void prep_transpose(const float* __restrict__ W1,
                               const float* __restrict__ W2) {
    const int total1 = N_MLP * S0 * S1;
    for (int idx = blockIdx.x * blockDim.x + threadIdx.x; idx < total1;
         idx += gridDim.x * blockDim.x) {
        int o = idx % S1;
        int k = (idx / S1) % S0;
        int m = idx / (S1 * S0);
        g_W1t[idx] = W1[((size_t)m * S1 + o) * S0 + k];
    }
    const int total2 = N_MLP * S1 * S2;
    for (int idx = blockIdx.x * blockDim.x + threadIdx.x; idx < total2;
         idx += gridDim.x * blockDim.x) {
        int o = idx % S2;
        int k = (idx / S2) % S1;
        int m = idx / (S2 * S1);
        g_W2t[idx] = W2[((size_t)m * S2 + o) * S1 + k];
    }
}

// ---------------- SMEM layout (floats) ------------------------------
// h0s  : [S0][TG]        0      .. 32768      (aliased by h2s [S2][65])
// h1s  : [S1][65]        32768  .. 49408
// w1s  : [16][S1]        49408  .. 53504      (aliased by w2s [16][S2])
// c0s  : 512             53504
// wxs  : 512             54016
// wys  : 512             54528
// b1s  : 256             55040
// b2s  : 128             55296
// w3s  : 384             55424
// b3s  : 4               55808
// gxs  : 64              55812
// gys  : 64              55876
#define SMEM_FLOATS 55940

__global__ __launch_bounds__(NTHR, 1)
void mlp_fused(const float* __restrict__ W0b,
               const float* __restrict__ b1,
               const float* __restrict__ b2,
               const float* __restrict__ W3,
               const float* __restrict__ b3,
               const int*   __restrict__ n_ptr,
               float*       __restrict__ out,
               int G) {
    extern __shared__ float sm[];
    float* h0s = sm;                 // 32768, also h2s
    float* h1s = sm + 32768;         // 16640 (pitch 65)
    float* w1s = sm + 49408;         // 4096, also w2s
    float* c0s = sm + 53504;
    float* wxs = sm + 54016;
    float* wys = sm + 54528;
    float* b1s = sm + 55040;
    float* b2s = sm + 55296;
    float* w3s = sm + 55424;
    float* b3s = sm + 55808;
    float* gxs = sm + 55812;
    float* gys = sm + 55876;

    const int m    = blockIdx.y;
    const int tile = blockIdx.x;
    const int tid  = threadIdx.x;
    const int n    = *n_ptr;

    // ---- stage per-MLP constants ----
    for (int i = tid; i < S0; i += NTHR) {
        c0s[i] = g_c0[m * S0 + i];
        wxs[i] = W0b[((size_t)m * S0 + i) * 2 + 0];
        wys[i] = W0b[((size_t)m * S0 + i) * 2 + 1];
    }
    for (int i = tid; i < S1; i += NTHR) b1s[i] = b1[m * S1 + i];
    for (int i = tid; i < S2; i += NTHR) b2s[i] = b2[m * S2 + i];
    for (int i = tid; i < OUTD * S2; i += NTHR) w3s[i] = W3[(size_t)m * OUTD * S2 + i];
    if (tid < OUTD) b3s[tid] = b3[m * OUTD + tid];
    if (tid < TG) {
        int p = tile * TG + tid;
        int px = 0, py = 0;
        if (p < G) { px = p % n; py = p / n; }
        float step = 2.0f / (float)(n - 1);
        gxs[tid] = -1.0f + step * (float)px;
        gys[tid] = -1.0f + step * (float)py;
    }
    __syncthreads();

    // ---- layer 0: h0s[o][g] = relu(c0[o] + wx[o]*gx + wy[o]*gy) ----
    for (int idx = tid; idx < S0 * TG; idx += NTHR) {
        int o = idx >> 6, g = idx & 63;
        float v = fmaf(wxs[o], gxs[g], fmaf(wys[o], gys[g], c0s[o]));
        h0s[idx] = fmaxf(v, 0.f);
    }

    // ---- layer 1: [TG x S1] = relu(h0[TG x S0] @ W1t) ----
    // acc packed over o-pairs: acc[i][j] = { (g0+i, o0+2j), (g0+i, o0+2j+1) }
    const int tcol = tid & 31, trow = tid >> 5;
    const int g0 = trow * 8;
    {
        const float* W1tm = g_W1t + (size_t)m * S0 * S1;
        const int o0 = tcol * 8;
        ull acc[8][4];
        {   // bias init (packed pairs, 32B-aligned: o0 multiple of 8)
            const ull* bp = (const ull*)(b1s + o0);
            #pragma unroll
            for (int i = 0; i < 8; ++i)
                #pragma unroll
                for (int j = 0; j < 4; ++j) acc[i][j] = bp[j];
        }

        for (int k0 = 0; k0 < S0; k0 += 16) {
            __syncthreads();   // previous stage consumed / layer0 writes done
            #pragma unroll
            for (int i = 0; i < 4; ++i) {
                int t = tid + i * NTHR;      // 1024 float4 per stage
                ((float4*)w1s)[t] = ((const float4*)(W1tm + (size_t)k0 * S1))[t];
            }
            __syncthreads();
            #pragma unroll
            for (int k = 0; k < 16; ++k) {
                const float* hr = h0s + (k0 + k) * TG + g0;
                float4 a0 = *(const float4*)hr;
                float4 a1 = *(const float4*)(hr + 4);
                float av[8] = {a0.x, a0.y, a0.z, a0.w, a1.x, a1.y, a1.z, a1.w};
                ull a2[8];
                #pragma unroll
                for (int i = 0; i < 8; ++i) a2[i] = pack2(av[i], av[i]);
                // natural 64-bit weight pairs (16B aligned)
                const ulonglong2* wr = (const ulonglong2*)(w1s + k * S1 + o0);
                ulonglong2 wA = wr[0], wB = wr[1];
                ull bv[4] = {wA.x, wA.y, wB.x, wB.y};
                #pragma unroll
                for (int i = 0; i < 8; ++i)
                    #pragma unroll
                    for (int j = 0; j < 4; ++j)
                        acc[i][j] = ffma2(a2[i], bv[j], acc[i][j]);
            }
        }
        // epilogue -> h1s[o][g], pitch 65
        #pragma unroll
        for (int j = 0; j < 4; ++j) {
            #pragma unroll
            for (int i = 0; i < 8; ++i) {
                float lo, hi;
                unpack2(acc[i][j], lo, hi);
                h1s[(o0 + 2 * j    ) * 65 + (g0 + i)] = fmaxf(lo, 0.f);
                h1s[(o0 + 2 * j + 1) * 65 + (g0 + i)] = fmaxf(hi, 0.f);
            }
        }
    }

    // ---- layer 2: [TG x S2] = relu(h1[TG x S1] @ W2t) ----
    {
        const float* W2tm = g_W2t + (size_t)m * S1 * S2;
        float* w2s = w1s;                  // alias
        const int o0 = tcol * 4;
        ull acc[8][2];
        {   // bias init (16B-aligned: o0 multiple of 4)
            const ull* bp = (const ull*)(b2s + o0);
            #pragma unroll
            for (int i = 0; i < 8; ++i) {
                acc[i][0] = bp[0];
                acc[i][1] = bp[1];
            }
        }

        for (int k0 = 0; k0 < S1; k0 += 16) {
            __syncthreads();   // h1s fully written / w1s consumers done
            #pragma unroll
            for (int i = 0; i < 2; ++i) {
                int t = tid + i * NTHR;      // 512 float4 per stage
                ((float4*)w2s)[t] = ((const float4*)(W2tm + (size_t)k0 * S2))[t];
            }
            __syncthreads();
            #pragma unroll
            for (int k = 0; k < 16; ++k) {
                const float* hr = h1s + (k0 + k) * 65 + g0;   // broadcast reads
                ull a2[8];
                #pragma unroll
                for (int i = 0; i < 8; ++i) { float h = hr[i]; a2[i] = pack2(h, h); }
                const ulonglong2* wr = (const ulonglong2*)(w2s + k * S2 + o0);
                ulonglong2 wA = wr[0];
                ull bv[2] = {wA.x, wA.y};
                #pragma unroll
                for (int i = 0; i < 8; ++i)
                    #pragma unroll
                    for (int j = 0; j < 2; ++j)
                        acc[i][j] = ffma2(a2[i], bv[j], acc[i][j]);
            }
        }
        // epilogue -> h2s[o][g], pitch 65 (aliases dead h0s)
        float* h2s = h0s;
        #pragma unroll
        for (int j = 0; j < 2; ++j) {
            #pragma unroll
            for (int i = 0; i < 8; ++i) {
                float lo, hi;
                unpack2(acc[i][j], lo, hi);
                h2s[(o0 + 2 * j    ) * 65 + (g0 + i)] = fmaxf(lo, 0.f);
                h2s[(o0 + 2 * j + 1) * 65 + (g0 + i)] = fmaxf(hi, 0.f);
            }
        }
    }
    __syncthreads();

    // ---- layer 3: out[g][o] = tanh(h2[g] . W3[o] + b3[o]) ----
    if (tid < TG * OUTD) {
        const float* h2s = h0s;
        int g = tid & 63;
        int o = tid >> 6;
        float s = b3s[o];
        const float* wr = w3s + o * S2;
        #pragma unroll 8
        for (int k = 0; k < S2; ++k) s = fmaf(h2s[k * 65 + g], wr[k], s);
        int p = tile * TG + g;
        if (p < G) out[((size_t)m * G + p) * OUTD + o] = tanhf(s);
    }
}

// ---------------- host launcher --------------------------------------
extern "C" void kernel_launch(void* const* d_in, const int* in_sizes, int n_in,
                              void* d_out, int out_size) {
    const float* x0  = (const float*)d_in[0];
    const float* W0a = (const float*)d_in[1];
    const float* b0a = (const float*)d_in[2];
    const float* W0b = (const float*)d_in[3];
    const float* b0b = (const float*)d_in[4];
    const float* W1  = (const float*)d_in[5];
    const float* b1  = (const float*)d_in[6];
    const float* W2  = (const float*)d_in[7];
    const float* b2  = (const float*)d_in[8];
    const float* W3  = (const float*)d_in[9];
    const float* b3  = (const float*)d_in[10];
    const int*   np  = (const int*)d_in[11];

    int G = out_size / (N_MLP * OUTD);   // grid points per MLP

    // prep
    prep_c0<<<(N_MLP * S0 * 32 + NTHR - 1) / NTHR, NTHR>>>(x0, W0a, b0a, b0b);
    prep_transpose<<<1024, NTHR>>>(W1, W2);

    // main fused kernel
    static bool attr_set = false;
    if (!attr_set) {
        cudaFuncSetAttribute(mlp_fused, cudaFuncAttributeMaxDynamicSharedMemorySize,
                             SMEM_FLOATS * sizeof(float));
        attr_set = true;
    }
    dim3 grid((G + TG - 1) / TG, N_MLP);
    mlp_fused<<<grid, NTHR, SMEM_FLOATS * sizeof(float)>>>(
        W0b, b1, b2, W3, b3, np, (float*)d_out, G);
}

// round 4
// speedup vs baseline: 2.5052x; 2.4695x over previous
#include <cuda_runtime.h>
#include <cuda_bf16.h>
#include <math.h>
#include <stdint.h>

#define N_MLP  16
#define LATENT 1024
#define S0     512
#define S1     256
#define S2     128
#define OUTD   3
#define TG     128
#define NTHR   256

// ---------------- SMEM byte offsets ---------------------------------
// h1 tiles q=0..3: hi at q*32K, lo at q*32K+16K          (0   .. 128K)
// chunk bufs: AHI 128K, ALO 144K, BHI 160K, BLO 176K     (128K.. 192K)
// h2 f32 [128][129] aliases h1 region (offset 0, 66KB)
// consts at 192K
#define H1HI_OFF(q) ((q)*32768u)
#define H1LO_OFF(q) ((q)*32768u + 16384u)
#define AHI_OFF 131072u
#define ALO_OFF 147456u
#define BHI_OFF 163840u
#define BLO_OFF 180224u
#define CONST_OFF 196608u
// const floats: c0f 0 | wxf 512 | wyf 1024 | b1f 1536 | b2f 1792 |
//               w3f 1920 | b3f 2304 | gxf 2308 | gyf 2436  -> 2564 floats
#define SMEM_TOTAL (CONST_OFF + 2564u * 4u)

#define SWZ(x) ((x) ^ (((x) >> 3) & 0x70u))

// ---------------- device scratch (16B-aligned for uint4 access) ------
__device__ __align__(16) __nv_bfloat16 g_W1hi[N_MLP * S1 * S0];
__device__ __align__(16) __nv_bfloat16 g_W1lo[N_MLP * S1 * S0];
__device__ __align__(16) __nv_bfloat16 g_W2hi[N_MLP * S2 * S1];
__device__ __align__(16) __nv_bfloat16 g_W2lo[N_MLP * S2 * S1];
__device__ float g_c0[N_MLP * S0];

// ---------------- helpers -------------------------------------------
__device__ __forceinline__ uint32_t smem_u32(const void* p) {
    uint32_t a;
    asm("{ .reg .u64 t; cvta.to.shared.u64 t, %1; cvt.u32.u64 %0, t; }"
        : "=r"(a) : "l"(p));
    return a;
}
__device__ __forceinline__ void ldsm4(uint32_t* r, uint32_t addr) {
    asm volatile("ldmatrix.sync.aligned.m8n8.x4.shared.b16 {%0,%1,%2,%3}, [%4];"
                 : "=r"(r[0]), "=r"(r[1]), "=r"(r[2]), "=r"(r[3]) : "r"(addr));
}
__device__ __forceinline__ void mma_bf16(float* d, const uint32_t* a, const uint32_t* b) {
    asm volatile(
        "mma.sync.aligned.m16n8k16.row.col.f32.bf16.bf16.f32 "
        "{%0,%1,%2,%3}, {%4,%5,%6,%7}, {%8,%9}, {%0,%1,%2,%3};"
        : "+f"(d[0]), "+f"(d[1]), "+f"(d[2]), "+f"(d[3])
        : "r"(a[0]), "r"(a[1]), "r"(a[2]), "r"(a[3]), "r"(b[0]), "r"(b[1]));
}
__device__ __forceinline__ void split2(float a, float b, uint32_t& hi, uint32_t& lo) {
    __nv_bfloat16 ha = __float2bfloat16(a), hb = __float2bfloat16(b);
    float ra = a - __bfloat162float(ha);
    float rb = b - __bfloat162float(hb);
    __nv_bfloat16 la = __float2bfloat16(ra), lb = __float2bfloat16(rb);
    hi = ((uint32_t)__bfloat16_as_ushort(hb) << 16) | (uint32_t)__bfloat16_as_ushort(ha);
    lo = ((uint32_t)__bfloat16_as_ushort(lb) << 16) | (uint32_t)__bfloat16_as_ushort(la);
}

// ---------------- prep kernels --------------------------------------
__global__ void prep_c0(const float* __restrict__ x0,
                        const float* __restrict__ W0a,
                        const float* __restrict__ b0a,
                        const float* __restrict__ b0b) {
    int w    = (blockIdx.x * blockDim.x + threadIdx.x) >> 5;
    int lane = threadIdx.x & 31;
    if (w >= N_MLP * S0) return;
    const float* row = W0a + (size_t)w * LATENT;
    float s = 0.f;
    #pragma unroll 4
    for (int i = lane; i < LATENT; i += 32) s += row[i] * x0[i];
    #pragma unroll
    for (int off = 16; off; off >>= 1) s += __shfl_xor_sync(0xffffffffu, s, off);
    if (lane == 0) g_c0[w] = s + b0a[w] + b0b[w];
}

__global__ void prep_split(const float* __restrict__ W1,
                           const float* __restrict__ W2) {
    const int t1 = N_MLP * S1 * S0;
    for (int i = blockIdx.x * blockDim.x + threadIdx.x; i < t1;
         i += gridDim.x * blockDim.x) {
        float v = W1[i];
        __nv_bfloat16 h = __float2bfloat16(v);
        g_W1hi[i] = h;
        g_W1lo[i] = __float2bfloat16(v - __bfloat162float(h));
    }
    const int t2 = N_MLP * S2 * S1;
    for (int i = blockIdx.x * blockDim.x + threadIdx.x; i < t2;
         i += gridDim.x * blockDim.x) {
        float v = W2[i];
        __nv_bfloat16 h = __float2bfloat16(v);
        g_W2hi[i] = h;
        g_W2lo[i] = __float2bfloat16(v - __bfloat162float(h));
    }
}

// ---------------- main HMMA kernel ------------------------------------
__global__ __launch_bounds__(NTHR, 1)
void mlp_hmma(const float* __restrict__ W0b,
              const float* __restrict__ b1,
              const float* __restrict__ b2,
              const float* __restrict__ W3,
              const float* __restrict__ b3,
              const int*   __restrict__ n_ptr,
              float*       __restrict__ out,
              int G) {
    extern __shared__ char smch[];
    const uint32_t smb = smem_u32(smch);
    float* c0f = (float*)(smch + CONST_OFF);
    float* wxf = c0f + 512;
    float* wyf = c0f + 1024;
    float* b1f = c0f + 1536;
    float* b2f = c0f + 1792;
    float* w3f = c0f + 1920;
    float* b3f = c0f + 2304;
    float* gxf = c0f + 2308;
    float* gyf = c0f + 2436;

    const int m    = blockIdx.y;
    const int tile = blockIdx.x;
    const int tid  = threadIdx.x;
    const int w    = tid >> 5;
    const int lane = tid & 31;
    const int n    = *n_ptr;

    // ---- stage per-MLP constants ----
    for (int i = tid; i < S0; i += NTHR) {
        c0f[i] = g_c0[m * S0 + i];
        wxf[i] = W0b[((size_t)m * S0 + i) * 2 + 0];
        wyf[i] = W0b[((size_t)m * S0 + i) * 2 + 1];
    }
    for (int i = tid; i < S1; i += NTHR) b1f[i] = b1[m * S1 + i];
    for (int i = tid; i < S2; i += NTHR) b2f[i] = b2[m * S2 + i];
    for (int i = tid; i < OUTD * S2; i += NTHR) w3f[i] = W3[(size_t)m * OUTD * S2 + i];
    if (tid < OUTD) b3f[tid] = b3[m * OUTD + tid];
    if (tid < TG) {
        int p = tile * TG + tid;
        int px = 0, py = 0;
        if (p < G) { px = p % n; py = p / n; }
        float step = 2.0f / (float)(n - 1);
        gxf[tid] = -1.0f + step * (float)px;
        gyf[tid] = -1.0f + step * (float)py;
    }
    __syncthreads();

    const int mw = w & 3, nw = w >> 2;
    const int m0 = mw * 32, n0 = nw * 64;
    const int r128 = tid & 127, half = tid >> 7;
    const float gxr = gxf[r128], gyr = gyf[r128];

    float C[2][8][4];

    // per-lane ldmatrix address pieces (byte offsets before SWZ)
    const uint32_t a_row = (uint32_t)(lane & 15);            // + m0 + mt*16
    const uint32_t a_col = (uint32_t)((lane >> 4) * 16);
    const uint32_t b_row = (uint32_t)((lane & 7) + ((lane & 16) >> 1)); // + n0 + nt2*16
    const uint32_t b_col = (uint32_t)(((lane >> 3) & 1) * 16);

    // =================== layer 1 =====================================
    for (int nh = 0; nh < 2; ++nh) {
        #pragma unroll
        for (int mt = 0; mt < 2; ++mt)
            #pragma unroll
            for (int nt = 0; nt < 8; ++nt) {
                int nn = nh * 128 + n0 + nt * 8 + (lane & 3) * 2;
                C[mt][nt][0] = b1f[nn];     C[mt][nt][1] = b1f[nn + 1];
                C[mt][nt][2] = b1f[nn];     C[mt][nt][3] = b1f[nn + 1];
            }

        for (int kc = 0; kc < 8; ++kc) {
            __syncthreads();
            // ---- stage A chunk: h0[:, kc*64 .. +64) hi/lo ----
            {
                char* ph = smch + AHI_OFF;
                char* pl = smch + ALO_OFF;
                #pragma unroll
                for (int i = 0; i < 8; ++i) {
                    int kl = half * 32 + i * 4;
                    int k  = kc * 64 + kl;
                    float4 c4 = *(const float4*)(c0f + k);
                    float4 x4 = *(const float4*)(wxf + k);
                    float4 y4 = *(const float4*)(wyf + k);
                    float v0 = fmaxf(fmaf(x4.x, gxr, fmaf(y4.x, gyr, c4.x)), 0.f);
                    float v1 = fmaxf(fmaf(x4.y, gxr, fmaf(y4.y, gyr, c4.y)), 0.f);
                    float v2 = fmaxf(fmaf(x4.z, gxr, fmaf(y4.z, gyr, c4.z)), 0.f);
                    float v3 = fmaxf(fmaf(x4.w, gxr, fmaf(y4.w, gyr, c4.w)), 0.f);
                    uint32_t h0u, l0u, h1u, l1u;
                    split2(v0, v1, h0u, l0u);
                    split2(v2, v3, h1u, l1u);
                    uint32_t off = SWZ((uint32_t)(r128 * 128 + kl * 2));
                    *(uint2*)(ph + off) = make_uint2(h0u, h1u);
                    *(uint2*)(pl + off) = make_uint2(l0u, l1u);
                }
            }
            // ---- stage B chunk: W1 rows [nh*128 .. +128), cols kc*64.. ----
            {
                const uint4* sh = (const uint4*)g_W1hi +
                                  ((size_t)m * 256 + nh * 128) * 64 + kc * 8;
                const uint4* sl = (const uint4*)g_W1lo +
                                  ((size_t)m * 256 + nh * 128) * 64 + kc * 8;
                char* dh = smch + BHI_OFF;
                char* dl = smch + BLO_OFF;
                #pragma unroll
                for (int jj = 0; jj < 4; ++jj) {
                    int idx = tid + jj * NTHR;          // 1024 uint4
                    int row = idx >> 3, c16 = idx & 7;
                    uint32_t off = SWZ((uint32_t)(row * 128 + c16 * 16));
                    *(uint4*)(dh + off) = sh[row * 64 + c16];
                    *(uint4*)(dl + off) = sl[row * 64 + c16];
                }
            }
            __syncthreads();
            // ---- mma over chunk ----
            #pragma unroll
            for (int k16 = 0; k16 < 4; ++k16) {
                const uint32_t kb2 = (uint32_t)(k16 * 32);
                uint32_t ahi[2][4], alo[2][4];
                #pragma unroll
                for (int mt = 0; mt < 2; ++mt) {
                    uint32_t aoff = SWZ((uint32_t)((m0 + mt * 16 + a_row) * 128) + kb2 + a_col);
                    ldsm4(ahi[mt], smb + AHI_OFF + aoff);
                    ldsm4(alo[mt], smb + ALO_OFF + aoff);
                }
                #pragma unroll
                for (int nt2 = 0; nt2 < 4; ++nt2) {
                    uint32_t boff = SWZ((uint32_t)((n0 + nt2 * 16 + b_row) * 128) + kb2 + b_col);
                    uint32_t bhi[4], blo[4];
                    ldsm4(bhi, smb + BHI_OFF + boff);
                    ldsm4(blo, smb + BLO_OFF + boff);
                    #pragma unroll
                    for (int mt = 0; mt < 2; ++mt)
                        #pragma unroll
                        for (int s = 0; s < 2; ++s) {
                            float* d = C[mt][nt2 * 2 + s];
                            mma_bf16(d, ahi[mt], bhi + 2 * s);
                            mma_bf16(d, ahi[mt], blo + 2 * s);
                            mma_bf16(d, alo[mt], bhi + 2 * s);
                        }
                }
            }
        }
        // ---- epilogue: relu + split -> h1 tiles ----
        #pragma unroll
        for (int mt = 0; mt < 2; ++mt) {
            int r = m0 + mt * 16 + (lane >> 2);
            #pragma unroll
            for (int nt = 0; nt < 8; ++nt) {
                int ng = nh * 128 + n0 + nt * 8 + (lane & 3) * 2;
                int q = ng >> 6, nc = ng & 63;
                uint32_t off  = SWZ((uint32_t)(r * 128 + nc * 2));
                uint32_t off2 = SWZ((uint32_t)((r + 8) * 128 + nc * 2));
                uint32_t hu, lu;
                split2(fmaxf(C[mt][nt][0], 0.f), fmaxf(C[mt][nt][1], 0.f), hu, lu);
                *(uint32_t*)(smch + H1HI_OFF(q) + off) = hu;
                *(uint32_t*)(smch + H1LO_OFF(q) + off) = lu;
                split2(fmaxf(C[mt][nt][2], 0.f), fmaxf(C[mt][nt][3], 0.f), hu, lu);
                *(uint32_t*)(smch + H1HI_OFF(q) + off2) = hu;
                *(uint32_t*)(smch + H1LO_OFF(q) + off2) = lu;
            }
        }
    }

    // =================== layer 2 =====================================
    #pragma unroll
    for (int mt = 0; mt < 2; ++mt)
        #pragma unroll
        for (int nt = 0; nt < 8; ++nt) {
            int nn = n0 + nt * 8 + (lane & 3) * 2;
            C[mt][nt][0] = b2f[nn];     C[mt][nt][1] = b2f[nn + 1];
            C[mt][nt][2] = b2f[nn];     C[mt][nt][3] = b2f[nn + 1];
        }

    for (int kc = 0; kc < 4; ++kc) {
        __syncthreads();
        {   // stage B2 chunk: W2 rows 0..128, cols kc*64..
            const uint4* sh = (const uint4*)g_W2hi + (size_t)m * 128 * 32 + kc * 8;
            const uint4* sl = (const uint4*)g_W2lo + (size_t)m * 128 * 32 + kc * 8;
            char* dh = smch + BHI_OFF;
            char* dl = smch + BLO_OFF;
            #pragma unroll
            for (int jj = 0; jj < 4; ++jj) {
                int idx = tid + jj * NTHR;
                int row = idx >> 3, c16 = idx & 7;
                uint32_t off = SWZ((uint32_t)(row * 128 + c16 * 16));
                *(uint4*)(dh + off) = sh[row * 32 + c16];
                *(uint4*)(dl + off) = sl[row * 32 + c16];
            }
        }
        __syncthreads();
        #pragma unroll
        for (int k16 = 0; k16 < 4; ++k16) {
            const uint32_t kb2 = (uint32_t)(k16 * 32);
            uint32_t ahi[2][4], alo[2][4];
            #pragma unroll
            for (int mt = 0; mt < 2; ++mt) {
                uint32_t aoff = SWZ((uint32_t)((m0 + mt * 16 + a_row) * 128) + kb2 + a_col);
                ldsm4(ahi[mt], smb + H1HI_OFF(kc) + aoff);
                ldsm4(alo[mt], smb + H1LO_OFF(kc) + aoff);
            }
            #pragma unroll
            for (int nt2 = 0; nt2 < 4; ++nt2) {
                uint32_t boff = SWZ((uint32_t)((n0 + nt2 * 16 + b_row) * 128) + kb2 + b_col);
                uint32_t bhi[4], blo[4];
                ldsm4(bhi, smb + BHI_OFF + boff);
                ldsm4(blo, smb + BLO_OFF + boff);
                #pragma unroll
                for (int mt = 0; mt < 2; ++mt)
                    #pragma unroll
                    for (int s = 0; s < 2; ++s) {
                        float* d = C[mt][nt2 * 2 + s];
                        mma_bf16(d, ahi[mt], bhi + 2 * s);
                        mma_bf16(d, ahi[mt], blo + 2 * s);
                        mma_bf16(d, alo[mt], bhi + 2 * s);
                    }
            }
        }
    }

    // ---- epilogue: relu -> h2 (f32, pitch 129, aliases h1 q0..q2) ----
    __syncthreads();
    float* h2s = (float*)smch;
    #pragma unroll
    for (int mt = 0; mt < 2; ++mt) {
        int r = m0 + mt * 16 + (lane >> 2);
        #pragma unroll
        for (int nt = 0; nt < 8; ++nt) {
            int nn = n0 + nt * 8 + (lane & 3) * 2;
            h2s[r * 129 + nn]           = fmaxf(C[mt][nt][0], 0.f);
            h2s[r * 129 + nn + 1]       = fmaxf(C[mt][nt][1], 0.f);
            h2s[(r + 8) * 129 + nn]     = fmaxf(C[mt][nt][2], 0.f);
            h2s[(r + 8) * 129 + nn + 1] = fmaxf(C[mt][nt][3], 0.f);
        }
    }
    __syncthreads();

    // =================== layer 3 + tanh ==============================
    if (tid < TG) {
        const float* hr = h2s + tid * 129;
        float a0 = b3f[0], a1 = b3f[1], a2 = b3f[2];
        #pragma unroll 8
        for (int k = 0; k < S2; ++k) {
            float h = hr[k];
            a0 = fmaf(h, w3f[k],        a0);
            a1 = fmaf(h, w3f[128 + k],  a1);
            a2 = fmaf(h, w3f[256 + k],  a2);
        }
        int p = tile * TG + tid;
        if (p < G) {
            float* o = out + ((size_t)m * G + p) * OUTD;
            o[0] = tanhf(a0);
            o[1] = tanhf(a1);
            o[2] = tanhf(a2);
        }
    }
}

// ---------------- host launcher --------------------------------------
extern "C" void kernel_launch(void* const* d_in, const int* in_sizes, int n_in,
                              void* d_out, int out_size) {
    const float* x0  = (const float*)d_in[0];
    const float* W0a = (const float*)d_in[1];
    const float* b0a = (const float*)d_in[2];
    const float* W0b = (const float*)d_in[3];
    const float* b0b = (const float*)d_in[4];
    const float* W1  = (const float*)d_in[5];
    const float* b1  = (const float*)d_in[6];
    const float* W2  = (const float*)d_in[7];
    const float* b2  = (const float*)d_in[8];
    const float* W3  = (const float*)d_in[9];
    const float* b3  = (const float*)d_in[10];
    const int*   np  = (const int*)d_in[11];

    int G = out_size / (N_MLP * OUTD);

    prep_c0<<<(N_MLP * S0 * 32 + NTHR - 1) / NTHR, NTHR>>>(x0, W0a, b0a, b0b);
    prep_split<<<1024, NTHR>>>(W1, W2);

    static bool attr_set = false;
    if (!attr_set) {
        cudaFuncSetAttribute(mlp_hmma, cudaFuncAttributeMaxDynamicSharedMemorySize,
                             SMEM_TOTAL);
        attr_set = true;
    }
    dim3 grid((G + TG - 1) / TG, N_MLP);
    mlp_hmma<<<grid, NTHR, SMEM_TOTAL>>>(W0b, b1, b2, W3, b3, np, (float*)d_out, G);
}